// round 6
// baseline (speedup 1.0000x reference)
#include <cuda_runtime.h>
#include <math.h>
#include <stdint.h>

namespace {
constexpr int kB = 512, kL = 256, kDin = 384, kD = 300;
constexpr int kMemRow = 13 * 8 * 300;             // 31200 floats / batch row of mem
constexpr int kMemOff = kB * kDin;                // 196608
constexpr int kLogitOff = kMemOff + kB * kMemRow; // 16171008
constexpr int kSlots = 4 * 13 * kD;               // 15600 floats of smem slots
constexpr int RECUR_SMEM = (kSlots + 8 * kD) * 4; // slots + 2x rs = 72000 B
constexpr int OUTG_SMEM = 8 * 3900 * 4;
}

typedef unsigned long long ull;

__device__ __forceinline__ void ffma2(ull& d, ull a, ull b, ull c) {
    asm("fma.rn.f32x2 %0, %1, %2, %3;" : "=l"(d) : "l"(a), "l"(b), "l"(c));
}
__device__ __forceinline__ float pairsum(ull v) {
    float lo = __uint_as_float((unsigned)(v & 0xffffffffu));
    float hi = __uint_as_float((unsigned)(v >> 32));
    return lo + hi;
}
__device__ __forceinline__ ull packf2(float lo, float hi) {
    ull r; asm("mov.b64 %0, {%1, %2};" : "=l"(r) : "f"(lo), "f"(hi)); return r;
}
__device__ __forceinline__ void unpackf2(ull v, float& lo, float& hi) {
    asm("mov.b64 {%0, %1}, %2;" : "=f"(lo), "=f"(hi) : "l"(v));
}

__device__ float g_U[(size_t)kL * kB * kD];  // [t][b][j]
__device__ float g_A[kDin * kD];             // in_W @ Wh0
__device__ float g_c0[kD];                   // in_b @ Wh0 + lb0
__device__ float g_WrT[kD * kD];             // Wr0^T: [j][k]
__device__ float g_x0[kB * kD];
__device__ float g_skip[kB * kDin];
__device__ float g_cpre[kB * kDin];

__global__ void prep_kernel(const float* __restrict__ in_W, const float* __restrict__ in_b,
                            const float* __restrict__ Wh, const float* __restrict__ Wr,
                            const float* __restrict__ lb) {
    int idx = blockIdx.x * blockDim.x + threadIdx.x;
    if (idx < kDin * kD) {
        int d = idx / kD, j = idx % kD;
        const float* iw = in_W + (size_t)d * kD;
        float s = 0.f;
        for (int k = 0; k < kD; k++) s += iw[k] * Wh[k * kD + j];
        g_A[idx] = s;
    } else if (idx < kDin * kD + kD * kD) {
        int t = idx - kDin * kD;
        int j = t / kD, k = t % kD;
        g_WrT[t] = Wr[k * kD + j];
    } else if (idx < kDin * kD + kD * kD + kD) {
        int j = idx - kDin * kD - kD * kD;
        float s = lb[j];
        for (int k = 0; k < kD; k++) s += in_b[k] * Wh[k * kD + j];
        g_c0[j] = s;
    }
}

// ---------------------------------------------------------------------------
// U = WE @ g_A + g_c0. BM=256, BN=64, BK=16; 256 thr; 8m x 8n per thread;
// FFMA2 paired along n. Warp layout mg=tid>>3 (4/warp), ng=tid&7 (8/warp):
// a-loads 8-way broadcast, b-loads 4-way broadcast -> crossbar ~free,
// FFMA2-pipe bound. Out row = l*512+b.
// ---------------------------------------------------------------------------
__global__ __launch_bounds__(256) void gemm_u_kernel(const float* __restrict__ we) {
    __shared__ float As[16][256];
    __shared__ float Bs[16][64];
    int tid = threadIdx.x;
    int row0 = blockIdx.y * 256, col0 = blockIdx.x * 64;
    int mg = tid >> 3, ng = tid & 7;     // m = mg*8.., n = ng*8..
    int colb = col0 + ng * 8;

    ull acc[8][4];
#pragma unroll
    for (int i = 0; i < 8; i++)
#pragma unroll
        for (int p = 0; p < 4; p++) acc[i][p] = 0ull;

    for (int k0 = 0; k0 < kDin; k0 += 16) {
        // A: thread tid loads we[row0+tid][k0..k0+15], stores transposed
#pragma unroll
        for (int i = 0; i < 4; i++) {
            float4 v = *(const float4*)&we[(size_t)(row0 + tid) * kDin + k0 + i * 4];
            As[i * 4 + 0][tid] = v.x; As[i * 4 + 1][tid] = v.y;
            As[i * 4 + 2][tid] = v.z; As[i * 4 + 3][tid] = v.w;
        }
        // B: one float4 per thread, direct store (n-contiguous)
        {
            int k = tid >> 4, n4 = (tid & 15) * 4;
            int col = col0 + n4;
            float4 v = make_float4(0.f, 0.f, 0.f, 0.f);
            if (col + 3 < kD) v = *(const float4*)&g_A[(size_t)(k0 + k) * kD + col];
            else {
                if (col     < kD) v.x = g_A[(k0 + k) * kD + col];
                if (col + 1 < kD) v.y = g_A[(k0 + k) * kD + col + 1];
                if (col + 2 < kD) v.z = g_A[(k0 + k) * kD + col + 2];
            }
            *(float4*)&Bs[k][n4] = v;
        }
        __syncthreads();
#pragma unroll
        for (int k = 0; k < 16; k++) {
            float4 a0 = *(const float4*)&As[k][mg * 8];
            float4 a1 = *(const float4*)&As[k][mg * 8 + 4];
            ulonglong2 b0 = *(const ulonglong2*)&Bs[k][ng * 8];
            ulonglong2 b1 = *(const ulonglong2*)&Bs[k][ng * 8 + 4];
            ull s[8];
            s[0] = packf2(a0.x, a0.x); s[1] = packf2(a0.y, a0.y);
            s[2] = packf2(a0.z, a0.z); s[3] = packf2(a0.w, a0.w);
            s[4] = packf2(a1.x, a1.x); s[5] = packf2(a1.y, a1.y);
            s[6] = packf2(a1.z, a1.z); s[7] = packf2(a1.w, a1.w);
#pragma unroll
            for (int i = 0; i < 8; i++) {
                ffma2(acc[i][0], s[i], b0.x, acc[i][0]);
                ffma2(acc[i][1], s[i], b0.y, acc[i][1]);
                ffma2(acc[i][2], s[i], b1.x, acc[i][2]);
                ffma2(acc[i][3], s[i], b1.y, acc[i][3]);
            }
        }
        __syncthreads();
    }

    float c0v[8];
#pragma unroll
    for (int p = 0; p < 8; p++) c0v[p] = (colb + p < kD) ? g_c0[colb + p] : 0.f;
#pragma unroll
    for (int i = 0; i < 8; i++) {
        int rin = row0 + mg * 8 + i;
        int orow = ((rin & 255) << 9) + (rin >> 8);
        float* op = g_U + (size_t)orow * kD;
        float r[8];
#pragma unroll
        for (int p = 0; p < 4; p++) unpackf2(acc[i][p], r[2 * p], r[2 * p + 1]);
#pragma unroll
        for (int p = 0; p < 8; p++) r[p] += c0v[p];
        if (colb + 7 < kD) {
            *(float4*)&op[colb]     = make_float4(r[0], r[1], r[2], r[3]);
            *(float4*)&op[colb + 4] = make_float4(r[4], r[5], r[6], r[7]);
        } else {
#pragma unroll
            for (int p = 0; p < 8; p++)
                if (colb + p < kD) op[colb + p] = r[p];
        }
    }
}

// ---------------------------------------------------------------------------
// Recurrence: 128 CTAs x 4 batch rows. Wr0 row j fully register-resident
// (75 ulonglong2). mem slots in smem, written to global once at the end.
// Per step: broadcast LDS.128 of r, FFMA2 accumulate, one barrier.
// ---------------------------------------------------------------------------
__global__ __launch_bounds__(320, 1) void recur_kernel(float* __restrict__ mem) {
    extern __shared__ float sm[];
    float* slots = sm;                // [4][13][kD]
    float* rsA = sm + kSlots;         // [4][kD]
    float* rsB = rsA + 4 * kD;        // [4][kD]
    int tid = threadIdx.x;
    int b0 = blockIdx.x * 4;

    for (int idx = tid; idx < kSlots; idx += blockDim.x) slots[idx] = 0.f;
    for (int idx = tid; idx < 4 * kD; idx += blockDim.x) { rsA[idx] = 0.f; rsB[idx] = 0.f; }

    const int j = tid;
    const bool act = (j < kD);

    ulonglong2 wreg[75];   // full Wr0^T row j (300 floats)
    if (act) {
#pragma unroll
        for (int q = 0; q < 75; q++)
            wreg[q] = *(const ulonglong2*)&g_WrT[(size_t)j * kD + 4 * q];
    }
    __syncthreads();

    const float inv13 = 1.f / 13.f;
    float* ra = rsA;
    float* rb = rsB;

    for (int t = 0; t < kL; t++) {
        int ptr = t % 13;
        if (act) {
            const float* up = g_U + ((size_t)t * kB + b0) * kD + j;
            float u0 = up[0], u1 = up[kD], u2 = up[2 * kD], u3 = up[3 * kD];
            float* sl = slots + ptr * kD + j;
            float o0 = sl[0], o1 = sl[13 * kD], o2 = sl[26 * kD], o3 = sl[39 * kD];

            ull a0x = 0, a0y = 0, a1x = 0, a1y = 0, a2x = 0, a2y = 0, a3x = 0, a3y = 0;
            const ulonglong2* r0p = (const ulonglong2*)(ra);
            const ulonglong2* r1p = (const ulonglong2*)(ra + kD);
            const ulonglong2* r2p = (const ulonglong2*)(ra + 2 * kD);
            const ulonglong2* r3p = (const ulonglong2*)(ra + 3 * kD);
#pragma unroll
            for (int q = 0; q < 75; q++) {
                ulonglong2 w = wreg[q];
                ulonglong2 q0 = r0p[q], q1 = r1p[q], q2 = r2p[q], q3 = r3p[q];
                ffma2(a0x, q0.x, w.x, a0x); ffma2(a0y, q0.y, w.y, a0y);
                ffma2(a1x, q1.x, w.x, a1x); ffma2(a1y, q1.y, w.y, a1y);
                ffma2(a2x, q2.x, w.x, a2x); ffma2(a2y, q2.y, w.y, a2y);
                ffma2(a3x, q3.x, w.x, a3x); ffma2(a3y, q3.y, w.y, a3y);
            }
            float h0 = tanhf(u0 + (pairsum(a0x) + pairsum(a0y)) * inv13);
            float h1 = tanhf(u1 + (pairsum(a1x) + pairsum(a1y)) * inv13);
            float h2 = tanhf(u2 + (pairsum(a2x) + pairsum(a2y)) * inv13);
            float h3 = tanhf(u3 + (pairsum(a3x) + pairsum(a3y)) * inv13);
            sl[0]       = h0;
            sl[13 * kD] = h1;
            sl[26 * kD] = h2;
            sl[39 * kD] = h3;
            rb[j]          = ra[j]          + (h0 - o0);
            rb[kD + j]     = ra[kD + j]     + (h1 - o1);
            rb[2 * kD + j] = ra[2 * kD + j] + (h2 - o2);
            rb[3 * kD + j] = ra[3 * kD + j] + (h3 - o3);
        }
        __syncthreads();
        float* tmp = ra; ra = rb; rb = tmp;
    }

    // write slots to global mem (layer-0 region)
    float* m0 = mem + (size_t)b0 * kMemRow;
    for (int idx = tid; idx < kSlots; idx += blockDim.x) {
        int row = idx / (13 * kD), rem = idx % (13 * kD);
        int ptr = rem / kD, jj = rem % kD;
        m0[(size_t)row * kMemRow + ptr * 2400 + jj] = slots[idx];
    }
}

__global__ void x0_kernel(const float* __restrict__ we, const float* __restrict__ in_W,
                          const float* __restrict__ in_b) {
    int idx = blockIdx.x * blockDim.x + threadIdx.x;
    if (idx >= kB * kD) return;
    int b = idx / kD, j = idx % kD;
    const float* wr = we + (size_t)b * kL * kDin;
    float s = in_b[j];
    for (int d = 0; d < kDin; d++) s += wr[d] * in_W[d * kD + j];
    g_x0[idx] = s;
}

__global__ void skip_kernel(const float* __restrict__ skip_W, const float* __restrict__ skip_b) {
    int idx = blockIdx.x * blockDim.x + threadIdx.x;
    if (idx >= kB * kDin) return;
    int b = idx / kDin, i = idx % kDin;
    const float* x = g_x0 + (size_t)b * kD;
    float s = skip_b[i];
    for (int jj = 0; jj < kD; jj++) s += x[jj] * skip_W[jj * kDin + i];
    g_skip[idx] = s;
}

// cpre = mem_layer0 @ out_W(layer0 rows). 64 CTAs x 8 rows, 384 threads, FFMA2.
__global__ void outgemm_kernel(const float* __restrict__ mem, const float* __restrict__ outW) {
    extern __shared__ float X[];  // [8][3900]
    int b0 = blockIdx.x * 8, tid = threadIdx.x;
    for (int idx = tid; idx < 8 * 3900; idx += 384) {
        int r = idx / 3900, k = idx % 3900;
        int s = k / 300, d = k % 300;
        X[idx] = mem[(size_t)(b0 + r) * kMemRow + s * 2400 + d];
    }
    __syncthreads();
    int i = tid;
    ull accx[8], accy[8];
#pragma unroll
    for (int r = 0; r < 8; r++) { accx[r] = 0ull; accy[r] = 0ull; }
    for (int s = 0; s < 13; s++) {
        const float* wb = outW + (size_t)s * 2400 * kDin + i;
        const float* Xs = X + s * 300;
        for (int d4 = 0; d4 < 75; d4++) {
            float w0 = wb[(size_t)(d4 * 4 + 0) * kDin];
            float w1 = wb[(size_t)(d4 * 4 + 1) * kDin];
            float w2 = wb[(size_t)(d4 * 4 + 2) * kDin];
            float w3 = wb[(size_t)(d4 * 4 + 3) * kDin];
            ull w01 = packf2(w0, w1), w23 = packf2(w2, w3);
#pragma unroll
            for (int r = 0; r < 8; r++) {
                ulonglong2 x = *(const ulonglong2*)&Xs[r * 3900 + d4 * 4];
                ffma2(accx[r], x.x, w01, accx[r]);
                ffma2(accy[r], x.y, w23, accy[r]);
            }
        }
    }
#pragma unroll
    for (int r = 0; r < 8; r++)
        g_cpre[(size_t)(b0 + r) * kDin + i] = pairsum(accx[r]) + pairsum(accy[r]);
}

__global__ void final_kernel(const float* __restrict__ out_b,
                             const float* __restrict__ ln_g, const float* __restrict__ ln_b,
                             const float* __restrict__ W1, const float* __restrict__ b1,
                             const float* __restrict__ W2, const float* __restrict__ b2,
                             float* __restrict__ out) {
    __shared__ float cv[kDin];
    __shared__ float red[16];
    __shared__ float hid[64];
    int b = blockIdx.x, tid = threadIdx.x;
    int lane = tid & 31, wid = tid >> 5;

    float v = g_cpre[(size_t)b * kDin + tid] + out_b[tid] + g_skip[(size_t)b * kDin + tid];

    float s = v;
#pragma unroll
    for (int o = 16; o > 0; o >>= 1) s += __shfl_xor_sync(0xffffffffu, s, o);
    if (lane == 0) red[wid] = s;
    __syncthreads();
    if (tid == 0) {
        float t = 0.f;
        for (int w = 0; w < 12; w++) t += red[w];
        red[12] = t / kDin;
    }
    __syncthreads();
    float mu = red[12];
    float dv = v - mu;
    float s2 = dv * dv;
#pragma unroll
    for (int o = 16; o > 0; o >>= 1) s2 += __shfl_xor_sync(0xffffffffu, s2, o);
    if (lane == 0) red[wid] = s2;
    __syncthreads();
    if (tid == 0) {
        float t = 0.f;
        for (int w = 0; w < 12; w++) t += red[w];
        red[13] = rsqrtf(t / kDin + 1e-5f);
    }
    __syncthreads();
    float c = dv * red[13] * ln_g[tid] + ln_b[tid];
    out[(size_t)b * kDin + tid] = c;
    cv[tid] = c;
    __syncthreads();

    if (tid < 64) {
        float a = b1[tid];
        for (int d = 0; d < kDin; d++) a += cv[d] * W1[(size_t)d * 64 + tid];
        hid[tid] = fmaxf(a, 0.f) * W2[tid];
    }
    __syncthreads();
    if (tid == 0) {
        float lg = b2[0];
        for (int h = 0; h < 64; h++) lg += hid[h];
        out[kLogitOff + b] = lg;
    }
}

extern "C" void kernel_launch(void* const* d_in, const int* in_sizes, int n_in,
                              void* d_out, int out_size) {
    const float* we     = (const float*)d_in[0];
    const float* in_W   = (const float*)d_in[1];
    const float* in_b   = (const float*)d_in[2];
    const float* Wh     = (const float*)d_in[3];
    const float* Wr     = (const float*)d_in[4];
    const float* lb     = (const float*)d_in[5];
    const float* skip_W = (const float*)d_in[6];
    const float* skip_b = (const float*)d_in[7];
    const float* out_W  = (const float*)d_in[8];
    const float* out_b  = (const float*)d_in[9];
    const float* ln_g   = (const float*)d_in[10];
    const float* ln_b   = (const float*)d_in[11];
    const float* sh_W1  = (const float*)d_in[12];
    const float* sh_b1  = (const float*)d_in[13];
    const float* sh_W2  = (const float*)d_in[14];
    const float* sh_b2  = (const float*)d_in[15];
    float* out = (float*)d_out;

    cudaFuncSetAttribute(recur_kernel, cudaFuncAttributeMaxDynamicSharedMemorySize, RECUR_SMEM);
    cudaFuncSetAttribute(outgemm_kernel, cudaFuncAttributeMaxDynamicSharedMemorySize, OUTG_SMEM);

    cudaMemsetAsync(out + kMemOff, 0, (size_t)kB * kMemRow * sizeof(float));       // item 1

    {
        int total = kDin * kD + kD * kD + kD;
        prep_kernel<<<(total + 255) / 256, 256>>>(in_W, in_b, Wh, Wr, lb);          // item 2
    }
    x0_kernel<<<(kB * kD + 255) / 256, 256>>>(we, in_W, in_b);                      // item 3
    {
        dim3 grid((kD + 63) / 64, (kB * kL) / 256);
        gemm_u_kernel<<<grid, 256>>>(we);                                           // item 4
    }
    recur_kernel<<<kB / 4, 320, RECUR_SMEM>>>(out + kMemOff);                       // item 5 (ncu slot)

    skip_kernel<<<(kB * kDin + 255) / 256, 256>>>(skip_W, skip_b);

    outgemm_kernel<<<kB / 8, 384, OUTG_SMEM>>>(out + kMemOff, out_W);

    final_kernel<<<kB, kDin>>>(out_b, ln_g, ln_b, sh_W1, sh_b1, sh_W2, sh_b2, out);
}

// round 7
// speedup vs baseline: 1.7176x; 1.7176x over previous
#include <cuda_runtime.h>
#include <math.h>
#include <stdint.h>

namespace {
constexpr int kB = 512, kL = 256, kDin = 384, kD = 300;
constexpr int kMemRow = 13 * 8 * 300;             // 31200 floats / batch row of mem
constexpr int kMemOff = kB * kDin;                // 196608
constexpr int kLogitOff = kMemOff + kB * kMemRow; // 16171008
constexpr int kSlots = 4 * 13 * kD;               // 15600 floats of smem slots
constexpr int KS = 128;                           // Wr0^T k-rows in smem
constexpr int WSTRIDE = 132;                      // padded row stride (floats)
constexpr int KT = kD - KS;                       // 172 tail k-rows in regs (43 ull2)
constexpr int RECUR_SMEM = (kD * WSTRIDE + kSlots + 8 * kD) * 4;  // 230400 B
constexpr int OUTG_SMEM = 8 * 3900 * 4;
}

typedef unsigned long long ull;

__device__ __forceinline__ void ffma2(ull& d, ull a, ull b, ull c) {
    asm("fma.rn.f32x2 %0, %1, %2, %3;" : "=l"(d) : "l"(a), "l"(b), "l"(c));
}
__device__ __forceinline__ float pairsum(ull v) {
    float lo = __uint_as_float((unsigned)(v & 0xffffffffu));
    float hi = __uint_as_float((unsigned)(v >> 32));
    return lo + hi;
}
__device__ __forceinline__ ull packf2(float lo, float hi) {
    ull r; asm("mov.b64 %0, {%1, %2};" : "=l"(r) : "f"(lo), "f"(hi)); return r;
}
__device__ __forceinline__ void unpackf2(ull v, float& lo, float& hi) {
    asm("mov.b64 {%0, %1}, %2;" : "=f"(lo), "=f"(hi) : "l"(v));
}

__device__ float g_U[(size_t)kL * kB * kD];  // [t][b][j]
__device__ float g_A[kDin * kD];             // in_W @ Wh0
__device__ float g_c0[kD];                   // in_b @ Wh0 + lb0
__device__ float g_WrT[kD * kD];             // Wr0^T: [j][k]
__device__ float g_x0[kB * kD];
__device__ float g_skip[kB * kDin];
__device__ float g_cpre[kB * kDin];

__global__ void prep_kernel(const float* __restrict__ in_W, const float* __restrict__ in_b,
                            const float* __restrict__ Wh, const float* __restrict__ Wr,
                            const float* __restrict__ lb) {
    int idx = blockIdx.x * blockDim.x + threadIdx.x;
    if (idx < kDin * kD) {
        int d = idx / kD, j = idx % kD;
        const float* iw = in_W + (size_t)d * kD;
        float s = 0.f;
        for (int k = 0; k < kD; k++) s += iw[k] * Wh[k * kD + j];
        g_A[idx] = s;
    } else if (idx < kDin * kD + kD * kD) {
        int t = idx - kDin * kD;
        int j = t / kD, k = t % kD;
        g_WrT[t] = Wr[k * kD + j];
    } else if (idx < kDin * kD + kD * kD + kD) {
        int j = idx - kDin * kD - kD * kD;
        float s = lb[j];
        for (int k = 0; k < kD; k++) s += in_b[k] * Wh[k * kD + j];
        g_c0[j] = s;
    }
}

// ---------------------------------------------------------------------------
// U = WE @ g_A + g_c0. BM=256, BN=64, BK=16; 256 thr; 8m x 8n per thread;
// FFMA2 paired along n; a-loads 8-way broadcast, b-loads conflict-free.
// ---------------------------------------------------------------------------
__global__ __launch_bounds__(256) void gemm_u_kernel(const float* __restrict__ we) {
    __shared__ float As[16][256];
    __shared__ float Bs[16][64];
    int tid = threadIdx.x;
    int row0 = blockIdx.y * 256, col0 = blockIdx.x * 64;
    int mg = tid >> 3, ng = tid & 7;
    int colb = col0 + ng * 8;

    ull acc[8][4];
#pragma unroll
    for (int i = 0; i < 8; i++)
#pragma unroll
        for (int p = 0; p < 4; p++) acc[i][p] = 0ull;

    for (int k0 = 0; k0 < kDin; k0 += 16) {
#pragma unroll
        for (int i = 0; i < 4; i++) {
            float4 v = *(const float4*)&we[(size_t)(row0 + tid) * kDin + k0 + i * 4];
            As[i * 4 + 0][tid] = v.x; As[i * 4 + 1][tid] = v.y;
            As[i * 4 + 2][tid] = v.z; As[i * 4 + 3][tid] = v.w;
        }
        {
            int k = tid >> 4, n4 = (tid & 15) * 4;
            int col = col0 + n4;
            float4 v = make_float4(0.f, 0.f, 0.f, 0.f);
            if (col + 3 < kD) v = *(const float4*)&g_A[(size_t)(k0 + k) * kD + col];
            else {
                if (col     < kD) v.x = g_A[(k0 + k) * kD + col];
                if (col + 1 < kD) v.y = g_A[(k0 + k) * kD + col + 1];
                if (col + 2 < kD) v.z = g_A[(k0 + k) * kD + col + 2];
            }
            *(float4*)&Bs[k][n4] = v;
        }
        __syncthreads();
#pragma unroll
        for (int k = 0; k < 16; k++) {
            float4 a0 = *(const float4*)&As[k][mg * 8];
            float4 a1 = *(const float4*)&As[k][mg * 8 + 4];
            ulonglong2 b0 = *(const ulonglong2*)&Bs[k][ng * 8];
            ulonglong2 b1 = *(const ulonglong2*)&Bs[k][ng * 8 + 4];
            ull s[8];
            s[0] = packf2(a0.x, a0.x); s[1] = packf2(a0.y, a0.y);
            s[2] = packf2(a0.z, a0.z); s[3] = packf2(a0.w, a0.w);
            s[4] = packf2(a1.x, a1.x); s[5] = packf2(a1.y, a1.y);
            s[6] = packf2(a1.z, a1.z); s[7] = packf2(a1.w, a1.w);
#pragma unroll
            for (int i = 0; i < 8; i++) {
                ffma2(acc[i][0], s[i], b0.x, acc[i][0]);
                ffma2(acc[i][1], s[i], b0.y, acc[i][1]);
                ffma2(acc[i][2], s[i], b1.x, acc[i][2]);
                ffma2(acc[i][3], s[i], b1.y, acc[i][3]);
            }
        }
        __syncthreads();
    }

    float c0v[8];
#pragma unroll
    for (int p = 0; p < 8; p++) c0v[p] = (colb + p < kD) ? g_c0[colb + p] : 0.f;
#pragma unroll
    for (int i = 0; i < 8; i++) {
        int rin = row0 + mg * 8 + i;
        int orow = ((rin & 255) << 9) + (rin >> 8);
        float* op = g_U + (size_t)orow * kD;
        float r[8];
#pragma unroll
        for (int p = 0; p < 4; p++) unpackf2(acc[i][p], r[2 * p], r[2 * p + 1]);
#pragma unroll
        for (int p = 0; p < 8; p++) r[p] += c0v[p];
        if (colb + 7 < kD) {
            *(float4*)&op[colb]     = make_float4(r[0], r[1], r[2], r[3]);
            *(float4*)&op[colb + 4] = make_float4(r[4], r[5], r[6], r[7]);
        } else {
#pragma unroll
            for (int p = 0; p < 8; p++)
                if (colb + p < kD) op[colb + p] = r[p];
        }
    }
}

// ---------------------------------------------------------------------------
// Recurrence: 128 CTAs x 4 batch rows. W split: KS=128 k-rows in smem
// (stride 132, conflict-free LDS.128), KT=172 k-rows in 86 regs (no spill).
// Slots live in smem; one global flush at the end. One barrier per step.
// ---------------------------------------------------------------------------
__global__ __launch_bounds__(320, 1) void recur_kernel(float* __restrict__ mem) {
    extern __shared__ float sm[];
    float* Ws    = sm;                         // [j][WSTRIDE]
    float* slots = sm + kD * WSTRIDE;          // [4][13][kD]
    float* rsA   = slots + kSlots;             // [4][kD]
    float* rsB   = rsA + 4 * kD;               // [4][kD]
    int tid = threadIdx.x;
    int b0 = blockIdx.x * 4;

    for (int idx = tid; idx < kD * (KS / 4); idx += blockDim.x) {
        int j = idx / (KS / 4), q = idx % (KS / 4);
        *(float4*)&Ws[j * WSTRIDE + q * 4] = *(const float4*)&g_WrT[(size_t)j * kD + q * 4];
    }
    for (int idx = tid; idx < kSlots; idx += blockDim.x) slots[idx] = 0.f;
    for (int idx = tid; idx < 4 * kD; idx += blockDim.x) { rsA[idx] = 0.f; rsB[idx] = 0.f; }

    const int j = tid;
    const bool act = (j < kD);

    ulonglong2 wr[KT / 4];   // 43 x 16B tail: k = 128..299
    if (act) {
#pragma unroll
        for (int q = 0; q < KT / 4; q++)
            wr[q] = *(const ulonglong2*)&g_WrT[(size_t)j * kD + KS + 4 * q];
    }
    __syncthreads();

    const float inv13 = 1.f / 13.f;
    float* ra = rsA;
    float* rb = rsB;

    for (int t = 0; t < kL; t++) {
        int ptr = t % 13;
        if (act) {
            const float* up = g_U + ((size_t)t * kB + b0) * kD + j;
            float u0 = up[0], u1 = up[kD], u2 = up[2 * kD], u3 = up[3 * kD];
            float* sl = slots + ptr * kD + j;
            float o0 = sl[0], o1 = sl[13 * kD], o2 = sl[26 * kD], o3 = sl[39 * kD];

            ull a0x = 0, a0y = 0, a1x = 0, a1y = 0, a2x = 0, a2y = 0, a3x = 0, a3y = 0;
            const ulonglong2* wp  = (const ulonglong2*)(Ws + j * WSTRIDE);
            const ulonglong2* r0p = (const ulonglong2*)(ra);
            const ulonglong2* r1p = (const ulonglong2*)(ra + kD);
            const ulonglong2* r2p = (const ulonglong2*)(ra + 2 * kD);
            const ulonglong2* r3p = (const ulonglong2*)(ra + 3 * kD);
#pragma unroll
            for (int q = 0; q < KS / 4; q++) {
                ulonglong2 w = wp[q];
                ulonglong2 q0 = r0p[q], q1 = r1p[q], q2 = r2p[q], q3 = r3p[q];
                ffma2(a0x, q0.x, w.x, a0x); ffma2(a0y, q0.y, w.y, a0y);
                ffma2(a1x, q1.x, w.x, a1x); ffma2(a1y, q1.y, w.y, a1y);
                ffma2(a2x, q2.x, w.x, a2x); ffma2(a2y, q2.y, w.y, a2y);
                ffma2(a3x, q3.x, w.x, a3x); ffma2(a3y, q3.y, w.y, a3y);
            }
#pragma unroll
            for (int q = 0; q < KT / 4; q++) {
                ulonglong2 w = wr[q];
                ulonglong2 q0 = r0p[KS / 4 + q], q1 = r1p[KS / 4 + q];
                ulonglong2 q2 = r2p[KS / 4 + q], q3 = r3p[KS / 4 + q];
                ffma2(a0x, q0.x, w.x, a0x); ffma2(a0y, q0.y, w.y, a0y);
                ffma2(a1x, q1.x, w.x, a1x); ffma2(a1y, q1.y, w.y, a1y);
                ffma2(a2x, q2.x, w.x, a2x); ffma2(a2y, q2.y, w.y, a2y);
                ffma2(a3x, q3.x, w.x, a3x); ffma2(a3y, q3.y, w.y, a3y);
            }
            float h0 = tanhf(u0 + (pairsum(a0x) + pairsum(a0y)) * inv13);
            float h1 = tanhf(u1 + (pairsum(a1x) + pairsum(a1y)) * inv13);
            float h2 = tanhf(u2 + (pairsum(a2x) + pairsum(a2y)) * inv13);
            float h3 = tanhf(u3 + (pairsum(a3x) + pairsum(a3y)) * inv13);
            sl[0]       = h0;
            sl[13 * kD] = h1;
            sl[26 * kD] = h2;
            sl[39 * kD] = h3;
            rb[j]          = ra[j]          + (h0 - o0);
            rb[kD + j]     = ra[kD + j]     + (h1 - o1);
            rb[2 * kD + j] = ra[2 * kD + j] + (h2 - o2);
            rb[3 * kD + j] = ra[3 * kD + j] + (h3 - o3);
        }
        __syncthreads();
        float* tmp = ra; ra = rb; rb = tmp;
    }

    float* m0 = mem + (size_t)b0 * kMemRow;
    for (int idx = tid; idx < kSlots; idx += blockDim.x) {
        int row = idx / (13 * kD), rem = idx % (13 * kD);
        int ptr = rem / kD, jj = rem % kD;
        m0[(size_t)row * kMemRow + ptr * 2400 + jj] = slots[idx];
    }
}

__global__ void x0_kernel(const float* __restrict__ we, const float* __restrict__ in_W,
                          const float* __restrict__ in_b) {
    int idx = blockIdx.x * blockDim.x + threadIdx.x;
    if (idx >= kB * kD) return;
    int b = idx / kD, j = idx % kD;
    const float* wr = we + (size_t)b * kL * kDin;
    float s = in_b[j];
    for (int d = 0; d < kDin; d++) s += wr[d] * in_W[d * kD + j];
    g_x0[idx] = s;
}

__global__ void skip_kernel(const float* __restrict__ skip_W, const float* __restrict__ skip_b) {
    int idx = blockIdx.x * blockDim.x + threadIdx.x;
    if (idx >= kB * kDin) return;
    int b = idx / kDin, i = idx % kDin;
    const float* x = g_x0 + (size_t)b * kD;
    float s = skip_b[i];
    for (int jj = 0; jj < kD; jj++) s += x[jj] * skip_W[jj * kDin + i];
    g_skip[idx] = s;
}

// cpre = mem_layer0 @ out_W(layer0 rows). 64 CTAs x 8 rows, 384 threads, FFMA2.
__global__ void outgemm_kernel(const float* __restrict__ mem, const float* __restrict__ outW) {
    extern __shared__ float X[];  // [8][3900]
    int b0 = blockIdx.x * 8, tid = threadIdx.x;
    for (int idx = tid; idx < 8 * 3900; idx += 384) {
        int r = idx / 3900, k = idx % 3900;
        int s = k / 300, d = k % 300;
        X[idx] = mem[(size_t)(b0 + r) * kMemRow + s * 2400 + d];
    }
    __syncthreads();
    int i = tid;
    ull accx[8], accy[8];
#pragma unroll
    for (int r = 0; r < 8; r++) { accx[r] = 0ull; accy[r] = 0ull; }
    for (int s = 0; s < 13; s++) {
        const float* wb = outW + (size_t)s * 2400 * kDin + i;
        const float* Xs = X + s * 300;
        for (int d4 = 0; d4 < 75; d4++) {
            float w0 = wb[(size_t)(d4 * 4 + 0) * kDin];
            float w1 = wb[(size_t)(d4 * 4 + 1) * kDin];
            float w2 = wb[(size_t)(d4 * 4 + 2) * kDin];
            float w3 = wb[(size_t)(d4 * 4 + 3) * kDin];
            ull w01 = packf2(w0, w1), w23 = packf2(w2, w3);
#pragma unroll
            for (int r = 0; r < 8; r++) {
                ulonglong2 x = *(const ulonglong2*)&Xs[r * 3900 + d4 * 4];
                ffma2(accx[r], x.x, w01, accx[r]);
                ffma2(accy[r], x.y, w23, accy[r]);
            }
        }
    }
#pragma unroll
    for (int r = 0; r < 8; r++)
        g_cpre[(size_t)(b0 + r) * kDin + i] = pairsum(accx[r]) + pairsum(accy[r]);
}

__global__ void final_kernel(const float* __restrict__ out_b,
                             const float* __restrict__ ln_g, const float* __restrict__ ln_b,
                             const float* __restrict__ W1, const float* __restrict__ b1,
                             const float* __restrict__ W2, const float* __restrict__ b2,
                             float* __restrict__ out) {
    __shared__ float cv[kDin];
    __shared__ float red[16];
    __shared__ float hid[64];
    int b = blockIdx.x, tid = threadIdx.x;
    int lane = tid & 31, wid = tid >> 5;

    float v = g_cpre[(size_t)b * kDin + tid] + out_b[tid] + g_skip[(size_t)b * kDin + tid];

    float s = v;
#pragma unroll
    for (int o = 16; o > 0; o >>= 1) s += __shfl_xor_sync(0xffffffffu, s, o);
    if (lane == 0) red[wid] = s;
    __syncthreads();
    if (tid == 0) {
        float t = 0.f;
        for (int w = 0; w < 12; w++) t += red[w];
        red[12] = t / kDin;
    }
    __syncthreads();
    float mu = red[12];
    float dv = v - mu;
    float s2 = dv * dv;
#pragma unroll
    for (int o = 16; o > 0; o >>= 1) s2 += __shfl_xor_sync(0xffffffffu, s2, o);
    if (lane == 0) red[wid] = s2;
    __syncthreads();
    if (tid == 0) {
        float t = 0.f;
        for (int w = 0; w < 12; w++) t += red[w];
        red[13] = rsqrtf(t / kDin + 1e-5f);
    }
    __syncthreads();
    float c = dv * red[13] * ln_g[tid] + ln_b[tid];
    out[(size_t)b * kDin + tid] = c;
    cv[tid] = c;
    __syncthreads();

    if (tid < 64) {
        float a = b1[tid];
        for (int d = 0; d < kDin; d++) a += cv[d] * W1[(size_t)d * 64 + tid];
        hid[tid] = fmaxf(a, 0.f) * W2[tid];
    }
    __syncthreads();
    if (tid == 0) {
        float lg = b2[0];
        for (int h = 0; h < 64; h++) lg += hid[h];
        out[kLogitOff + b] = lg;
    }
}

extern "C" void kernel_launch(void* const* d_in, const int* in_sizes, int n_in,
                              void* d_out, int out_size) {
    const float* we     = (const float*)d_in[0];
    const float* in_W   = (const float*)d_in[1];
    const float* in_b   = (const float*)d_in[2];
    const float* Wh     = (const float*)d_in[3];
    const float* Wr     = (const float*)d_in[4];
    const float* lb     = (const float*)d_in[5];
    const float* skip_W = (const float*)d_in[6];
    const float* skip_b = (const float*)d_in[7];
    const float* out_W  = (const float*)d_in[8];
    const float* out_b  = (const float*)d_in[9];
    const float* ln_g   = (const float*)d_in[10];
    const float* ln_b   = (const float*)d_in[11];
    const float* sh_W1  = (const float*)d_in[12];
    const float* sh_b1  = (const float*)d_in[13];
    const float* sh_W2  = (const float*)d_in[14];
    const float* sh_b2  = (const float*)d_in[15];
    float* out = (float*)d_out;

    cudaFuncSetAttribute(recur_kernel, cudaFuncAttributeMaxDynamicSharedMemorySize, RECUR_SMEM);
    cudaFuncSetAttribute(outgemm_kernel, cudaFuncAttributeMaxDynamicSharedMemorySize, OUTG_SMEM);

    cudaMemsetAsync(out + kMemOff, 0, (size_t)kB * kMemRow * sizeof(float));       // item 1

    {
        int total = kDin * kD + kD * kD + kD;
        prep_kernel<<<(total + 255) / 256, 256>>>(in_W, in_b, Wh, Wr, lb);          // item 2
    }
    x0_kernel<<<(kB * kD + 255) / 256, 256>>>(we, in_W, in_b);                      // item 3
    {
        dim3 grid((kD + 63) / 64, (kB * kL) / 256);
        gemm_u_kernel<<<grid, 256>>>(we);                                           // item 4
    }
    recur_kernel<<<kB / 4, 320, RECUR_SMEM>>>(out + kMemOff);                       // item 5 (ncu slot)

    skip_kernel<<<(kB * kDin + 255) / 256, 256>>>(skip_W, skip_b);

    outgemm_kernel<<<kB / 8, 384, OUTG_SMEM>>>(out + kMemOff, out_W);

    final_kernel<<<kB, kDin>>>(out_b, ln_g, ln_b, sh_W1, sh_b1, sh_W2, sh_b2, out);
}

// round 9
// speedup vs baseline: 2.5614x; 1.4912x over previous
#include <cuda_runtime.h>
#include <math.h>
#include <stdint.h>

namespace {
constexpr int kB = 512, kL = 256, kDin = 384, kD = 300;
constexpr int kMemRow = 13 * 8 * 300;             // 31200 floats / batch row of mem
constexpr int kMemOff = kB * kDin;                // 196608
constexpr int kLogitOff = kMemOff + kB * kMemRow; // 16171008
constexpr int KS = 180;                           // Wr0^T k-rows cached in smem
constexpr int KT = kD - KS;                       // 120 tail k-rows in registers
constexpr int RECUR_SMEM = (kD * KS + 8 * kD) * 4;   // Ws + 2x rs buffers = 225600 B
constexpr int OUTG_SMEM = 8 * 3900 * 4;
}

typedef unsigned long long ull;

__device__ __forceinline__ void ffma2(ull& d, ull a, ull b, ull c) {
    asm("fma.rn.f32x2 %0, %1, %2, %3;" : "=l"(d) : "l"(a), "l"(b), "l"(c));
}
__device__ __forceinline__ float pairsum(ull v) {
    float lo = __uint_as_float((unsigned)(v & 0xffffffffu));
    float hi = __uint_as_float((unsigned)(v >> 32));
    return lo + hi;
}
__device__ __forceinline__ ull packf2(float lo, float hi) {
    ull r; asm("mov.b64 %0, {%1, %2};" : "=l"(r) : "f"(lo), "f"(hi)); return r;
}
__device__ __forceinline__ void unpackf2(ull v, float& lo, float& hi) {
    asm("mov.b64 {%0, %1}, %2;" : "=f"(lo), "=f"(hi) : "l"(v));
}

__device__ float g_U[(size_t)kL * kB * kD];  // [t][b][j]
__device__ float g_A[kDin * kD];             // in_W @ Wh0
__device__ float g_c0[kD];                   // in_b @ Wh0 + lb0
__device__ float g_WrT[kD * kD];             // Wr0^T: [j][k]
__device__ float g_x0[kB * kD];
__device__ float g_skip[kB * kDin];
__device__ float g_cpre[kB * kDin];

__global__ void prep_kernel(const float* __restrict__ in_W, const float* __restrict__ in_b,
                            const float* __restrict__ Wh, const float* __restrict__ Wr,
                            const float* __restrict__ lb) {
    int idx = blockIdx.x * blockDim.x + threadIdx.x;
    if (idx < kDin * kD) {
        int d = idx / kD, j = idx % kD;
        const float* iw = in_W + (size_t)d * kD;
        float s = 0.f;
        for (int k = 0; k < kD; k++) s += iw[k] * Wh[k * kD + j];
        g_A[idx] = s;
    } else if (idx < kDin * kD + kD * kD) {
        int t = idx - kDin * kD;
        int j = t / kD, k = t % kD;
        g_WrT[t] = Wr[k * kD + j];
    } else if (idx < kDin * kD + kD * kD + kD) {
        int j = idx - kDin * kD - kD * kD;
        float s = lb[j];
        for (int k = 0; k < kD; k++) s += in_b[k] * Wh[k * kD + j];
        g_c0[j] = s;
    }
}

// ---------------------------------------------------------------------------
// U = WE @ g_A + g_c0. BM=256, BN=64, BK=16; 256 thr; 8m x 8n per thread;
// FFMA2 paired along n; a-loads 8-way broadcast, b-loads conflict-free.
// ---------------------------------------------------------------------------
__global__ __launch_bounds__(256) void gemm_u_kernel(const float* __restrict__ we) {
    __shared__ float As[16][256];
    __shared__ float Bs[16][64];
    int tid = threadIdx.x;
    int row0 = blockIdx.y * 256, col0 = blockIdx.x * 64;
    int mg = tid >> 3, ng = tid & 7;
    int colb = col0 + ng * 8;

    ull acc[8][4];
#pragma unroll
    for (int i = 0; i < 8; i++)
#pragma unroll
        for (int p = 0; p < 4; p++) acc[i][p] = 0ull;

    for (int k0 = 0; k0 < kDin; k0 += 16) {
#pragma unroll
        for (int i = 0; i < 4; i++) {
            float4 v = *(const float4*)&we[(size_t)(row0 + tid) * kDin + k0 + i * 4];
            As[i * 4 + 0][tid] = v.x; As[i * 4 + 1][tid] = v.y;
            As[i * 4 + 2][tid] = v.z; As[i * 4 + 3][tid] = v.w;
        }
        {
            int k = tid >> 4, n4 = (tid & 15) * 4;
            int col = col0 + n4;
            float4 v = make_float4(0.f, 0.f, 0.f, 0.f);
            if (col + 3 < kD) v = *(const float4*)&g_A[(size_t)(k0 + k) * kD + col];
            else {
                if (col     < kD) v.x = g_A[(k0 + k) * kD + col];
                if (col + 1 < kD) v.y = g_A[(k0 + k) * kD + col + 1];
                if (col + 2 < kD) v.z = g_A[(k0 + k) * kD + col + 2];
            }
            *(float4*)&Bs[k][n4] = v;
        }
        __syncthreads();
#pragma unroll
        for (int k = 0; k < 16; k++) {
            float4 a0 = *(const float4*)&As[k][mg * 8];
            float4 a1 = *(const float4*)&As[k][mg * 8 + 4];
            ulonglong2 b0 = *(const ulonglong2*)&Bs[k][ng * 8];
            ulonglong2 b1 = *(const ulonglong2*)&Bs[k][ng * 8 + 4];
            ull s[8];
            s[0] = packf2(a0.x, a0.x); s[1] = packf2(a0.y, a0.y);
            s[2] = packf2(a0.z, a0.z); s[3] = packf2(a0.w, a0.w);
            s[4] = packf2(a1.x, a1.x); s[5] = packf2(a1.y, a1.y);
            s[6] = packf2(a1.z, a1.z); s[7] = packf2(a1.w, a1.w);
#pragma unroll
            for (int i = 0; i < 8; i++) {
                ffma2(acc[i][0], s[i], b0.x, acc[i][0]);
                ffma2(acc[i][1], s[i], b0.y, acc[i][1]);
                ffma2(acc[i][2], s[i], b1.x, acc[i][2]);
                ffma2(acc[i][3], s[i], b1.y, acc[i][3]);
            }
        }
        __syncthreads();
    }

    float c0v[8];
#pragma unroll
    for (int p = 0; p < 8; p++) c0v[p] = (colb + p < kD) ? g_c0[colb + p] : 0.f;
#pragma unroll
    for (int i = 0; i < 8; i++) {
        int rin = row0 + mg * 8 + i;
        int orow = ((rin & 255) << 9) + (rin >> 8);
        float* op = g_U + (size_t)orow * kD;
        float r[8];
#pragma unroll
        for (int p = 0; p < 4; p++) unpackf2(acc[i][p], r[2 * p], r[2 * p + 1]);
#pragma unroll
        for (int p = 0; p < 8; p++) r[p] += c0v[p];
        if (colb + 7 < kD) {
            *(float4*)&op[colb]     = make_float4(r[0], r[1], r[2], r[3]);
            *(float4*)&op[colb + 4] = make_float4(r[4], r[5], r[6], r[7]);
        } else {
#pragma unroll
            for (int p = 0; p < 8; p++)
                if (colb + p < kD) op[colb + p] = r[p];
        }
    }
}

// ---------------------------------------------------------------------------
// Recurrence (R5-exact): 128 CTAs x 4 batch rows. LDS.128 operands, FFMA2,
// single barrier per step via rs double-buffer. KS=180 smem + 60-reg tail.
// Slots live in global mem (L2-resident per CTA).
// ---------------------------------------------------------------------------
__global__ __launch_bounds__(320, 1) void recur_kernel(float* __restrict__ mem) {
    extern __shared__ float sm[];
    float* Ws  = sm;                 // [j][KS] stride 180 floats (16B aligned rows)
    float* rsA = sm + kD * KS;       // [4][kD]
    float* rsB = rsA + 4 * kD;       // [4][kD]
    int tid = threadIdx.x;
    int b0 = blockIdx.x * 4;

    for (int idx = tid; idx < kD * (KS / 4); idx += blockDim.x) {
        int j = idx / (KS / 4), q = idx % (KS / 4);
        *(float4*)&Ws[j * KS + q * 4] = *(const float4*)&g_WrT[(size_t)j * kD + q * 4];
    }
    for (int idx = tid; idx < 4 * kD; idx += blockDim.x) { rsA[idx] = 0.f; rsB[idx] = 0.f; }

    const int j = tid;
    const bool act = (j < kD);

    ulonglong2 wr[KT / 4];  // 30 x 16B = tail k=180..299 of row j
    if (act) {
#pragma unroll
        for (int i = 0; i < KT / 4; i++)
            wr[i] = *(const ulonglong2*)&g_WrT[(size_t)j * kD + KS + 4 * i];
    }
    __syncthreads();

    float* m0 = mem + (size_t)b0 * kMemRow;
    const float inv13 = 1.f / 13.f;
    float* ra = rsA;
    float* rb = rsB;

    for (int t = 0; t < kL; t++) {
        int ptr = t % 13;
        if (act) {
            const float* up = g_U + ((size_t)t * kB + b0) * kD + j;
            float u0 = up[0], u1 = up[kD], u2 = up[2 * kD], u3 = up[3 * kD];
            float* ms = m0 + ptr * 2400 + j;
            float o0 = ms[0], o1 = ms[kMemRow], o2 = ms[2 * kMemRow], o3 = ms[3 * kMemRow];

            ull a0x = 0, a0y = 0, a1x = 0, a1y = 0, a2x = 0, a2y = 0, a3x = 0, a3y = 0;
            const ulonglong2* wp  = (const ulonglong2*)(Ws + j * KS);
            const ulonglong2* r0p = (const ulonglong2*)(ra);
            const ulonglong2* r1p = (const ulonglong2*)(ra + kD);
            const ulonglong2* r2p = (const ulonglong2*)(ra + 2 * kD);
            const ulonglong2* r3p = (const ulonglong2*)(ra + 3 * kD);
#pragma unroll
            for (int q = 0; q < KS / 4; q++) {
                ulonglong2 w = wp[q];
                ulonglong2 q0 = r0p[q], q1 = r1p[q], q2 = r2p[q], q3 = r3p[q];
                ffma2(a0x, q0.x, w.x, a0x); ffma2(a0y, q0.y, w.y, a0y);
                ffma2(a1x, q1.x, w.x, a1x); ffma2(a1y, q1.y, w.y, a1y);
                ffma2(a2x, q2.x, w.x, a2x); ffma2(a2y, q2.y, w.y, a2y);
                ffma2(a3x, q3.x, w.x, a3x); ffma2(a3y, q3.y, w.y, a3y);
            }
#pragma unroll
            for (int q = 0; q < KT / 4; q++) {
                ulonglong2 w = wr[q];
                ulonglong2 q0 = r0p[KS / 4 + q], q1 = r1p[KS / 4 + q];
                ulonglong2 q2 = r2p[KS / 4 + q], q3 = r3p[KS / 4 + q];
                ffma2(a0x, q0.x, w.x, a0x); ffma2(a0y, q0.y, w.y, a0y);
                ffma2(a1x, q1.x, w.x, a1x); ffma2(a1y, q1.y, w.y, a1y);
                ffma2(a2x, q2.x, w.x, a2x); ffma2(a2y, q2.y, w.y, a2y);
                ffma2(a3x, q3.x, w.x, a3x); ffma2(a3y, q3.y, w.y, a3y);
            }
            float h0 = tanhf(u0 + (pairsum(a0x) + pairsum(a0y)) * inv13);
            float h1 = tanhf(u1 + (pairsum(a1x) + pairsum(a1y)) * inv13);
            float h2 = tanhf(u2 + (pairsum(a2x) + pairsum(a2y)) * inv13);
            float h3 = tanhf(u3 + (pairsum(a3x) + pairsum(a3y)) * inv13);
            ms[0]           = h0;
            ms[kMemRow]     = h1;
            ms[2 * kMemRow] = h2;
            ms[3 * kMemRow] = h3;
            rb[j]          = ra[j]          + (h0 - o0);
            rb[kD + j]     = ra[kD + j]     + (h1 - o1);
            rb[2 * kD + j] = ra[2 * kD + j] + (h2 - o2);
            rb[3 * kD + j] = ra[3 * kD + j] + (h3 - o3);
        }
        __syncthreads();
        float* tmp = ra; ra = rb; rb = tmp;
    }
}

__global__ void x0_kernel(const float* __restrict__ we, const float* __restrict__ in_W,
                          const float* __restrict__ in_b) {
    int idx = blockIdx.x * blockDim.x + threadIdx.x;
    if (idx >= kB * kD) return;
    int b = idx / kD, j = idx % kD;
    const float* wr = we + (size_t)b * kL * kDin;
    float s = in_b[j];
    for (int d = 0; d < kDin; d++) s += wr[d] * in_W[d * kD + j];
    g_x0[idx] = s;
}

__global__ void skip_kernel(const float* __restrict__ skip_W, const float* __restrict__ skip_b) {
    int idx = blockIdx.x * blockDim.x + threadIdx.x;
    if (idx >= kB * kDin) return;
    int b = idx / kDin, i = idx % kDin;
    const float* x = g_x0 + (size_t)b * kD;
    float s = skip_b[i];
    for (int jj = 0; jj < kD; jj++) s += x[jj] * skip_W[jj * kDin + i];
    g_skip[idx] = s;
}

// cpre = mem_layer0 @ out_W(layer0 rows). 64 CTAs x 8 rows, 384 threads, FFMA2.
__global__ void outgemm_kernel(const float* __restrict__ mem, const float* __restrict__ outW) {
    extern __shared__ float X[];  // [8][3900]
    int b0 = blockIdx.x * 8, tid = threadIdx.x;
    for (int idx = tid; idx < 8 * 3900; idx += 384) {
        int r = idx / 3900, k = idx % 3900;
        int s = k / 300, d = k % 300;
        X[idx] = mem[(size_t)(b0 + r) * kMemRow + s * 2400 + d];
    }
    __syncthreads();
    int i = tid;
    ull accx[8], accy[8];
#pragma unroll
    for (int r = 0; r < 8; r++) { accx[r] = 0ull; accy[r] = 0ull; }
    for (int s = 0; s < 13; s++) {
        const float* wb = outW + (size_t)s * 2400 * kDin + i;
        const float* Xs = X + s * 300;
        for (int d4 = 0; d4 < 75; d4++) {
            float w0 = wb[(size_t)(d4 * 4 + 0) * kDin];
            float w1 = wb[(size_t)(d4 * 4 + 1) * kDin];
            float w2 = wb[(size_t)(d4 * 4 + 2) * kDin];
            float w3 = wb[(size_t)(d4 * 4 + 3) * kDin];
            ull w01 = packf2(w0, w1), w23 = packf2(w2, w3);
#pragma unroll
            for (int r = 0; r < 8; r++) {
                ulonglong2 x = *(const ulonglong2*)&Xs[r * 3900 + d4 * 4];
                ffma2(accx[r], x.x, w01, accx[r]);
                ffma2(accy[r], x.y, w23, accy[r]);
            }
        }
    }
#pragma unroll
    for (int r = 0; r < 8; r++)
        g_cpre[(size_t)(b0 + r) * kDin + i] = pairsum(accx[r]) + pairsum(accy[r]);
}

__global__ void final_kernel(const float* __restrict__ out_b,
                             const float* __restrict__ ln_g, const float* __restrict__ ln_b,
                             const float* __restrict__ W1, const float* __restrict__ b1,
                             const float* __restrict__ W2, const float* __restrict__ b2,
                             float* __restrict__ out) {
    __shared__ float cv[kDin];
    __shared__ float red[16];
    __shared__ float hid[64];
    int b = blockIdx.x, tid = threadIdx.x;
    int lane = tid & 31, wid = tid >> 5;

    float v = g_cpre[(size_t)b * kDin + tid] + out_b[tid] + g_skip[(size_t)b * kDin + tid];

    float s = v;
#pragma unroll
    for (int o = 16; o > 0; o >>= 1) s += __shfl_xor_sync(0xffffffffu, s, o);
    if (lane == 0) red[wid] = s;
    __syncthreads();
    if (tid == 0) {
        float t = 0.f;
        for (int w = 0; w < 12; w++) t += red[w];
        red[12] = t / kDin;
    }
    __syncthreads();
    float mu = red[12];
    float dv = v - mu;
    float s2 = dv * dv;
#pragma unroll
    for (int o = 16; o > 0; o >>= 1) s2 += __shfl_xor_sync(0xffffffffu, s2, o);
    if (lane == 0) red[wid] = s2;
    __syncthreads();
    if (tid == 0) {
        float t = 0.f;
        for (int w = 0; w < 12; w++) t += red[w];
        red[13] = rsqrtf(t / kDin + 1e-5f);
    }
    __syncthreads();
    float c = dv * red[13] * ln_g[tid] + ln_b[tid];
    out[(size_t)b * kDin + tid] = c;
    cv[tid] = c;
    __syncthreads();

    if (tid < 64) {
        float a = b1[tid];
        for (int d = 0; d < kDin; d++) a += cv[d] * W1[(size_t)d * 64 + tid];
        hid[tid] = fmaxf(a, 0.f) * W2[tid];
    }
    __syncthreads();
    if (tid == 0) {
        float lg = b2[0];
        for (int h = 0; h < 64; h++) lg += hid[h];
        out[kLogitOff + b] = lg;
    }
}

extern "C" void kernel_launch(void* const* d_in, const int* in_sizes, int n_in,
                              void* d_out, int out_size) {
    const float* we     = (const float*)d_in[0];
    const float* in_W   = (const float*)d_in[1];
    const float* in_b   = (const float*)d_in[2];
    const float* Wh     = (const float*)d_in[3];
    const float* Wr     = (const float*)d_in[4];
    const float* lb     = (const float*)d_in[5];
    const float* skip_W = (const float*)d_in[6];
    const float* skip_b = (const float*)d_in[7];
    const float* out_W  = (const float*)d_in[8];
    const float* out_b  = (const float*)d_in[9];
    const float* ln_g   = (const float*)d_in[10];
    const float* ln_b   = (const float*)d_in[11];
    const float* sh_W1  = (const float*)d_in[12];
    const float* sh_b1  = (const float*)d_in[13];
    const float* sh_W2  = (const float*)d_in[14];
    const float* sh_b2  = (const float*)d_in[15];
    float* out = (float*)d_out;

    cudaFuncSetAttribute(recur_kernel, cudaFuncAttributeMaxDynamicSharedMemorySize, RECUR_SMEM);
    cudaFuncSetAttribute(outgemm_kernel, cudaFuncAttributeMaxDynamicSharedMemorySize, OUTG_SMEM);

    cudaMemsetAsync(out + kMemOff, 0, (size_t)kB * kMemRow * sizeof(float));       // item 1

    {
        int total = kDin * kD + kD * kD + kD;
        prep_kernel<<<(total + 255) / 256, 256>>>(in_W, in_b, Wh, Wr, lb);          // item 2
    }
    x0_kernel<<<(kB * kD + 255) / 256, 256>>>(we, in_W, in_b);                      // item 3
    skip_kernel<<<(kB * kDin + 255) / 256, 256>>>(skip_W, skip_b);                  // item 4
    {
        dim3 grid((kD + 63) / 64, (kB * kL) / 256);
        gemm_u_kernel<<<grid, 256>>>(we);                                           // item 5 (ncu slot)
    }
    recur_kernel<<<kB / 4, 320, RECUR_SMEM>>>(out + kMemOff);

    outgemm_kernel<<<kB / 8, 384, OUTG_SMEM>>>(out + kMemOff, out_W);

    final_kernel<<<kB, kDin>>>(out_b, ln_g, ln_b, sh_W1, sh_b1, sh_W2, sh_b2, out);
}

// round 10
// speedup vs baseline: 2.7990x; 1.0928x over previous
#include <cuda_runtime.h>
#include <math.h>
#include <stdint.h>

namespace {
constexpr int kB = 512, kL = 256, kDin = 384, kD = 300;
constexpr int kMemRow = 13 * 8 * 300;             // 31200 floats / batch row of mem
constexpr int kMemOff = kB * kDin;                // 196608
constexpr int kLogitOff = kMemOff + kB * kMemRow; // 16171008
constexpr int KS = 180;                           // Wr0^T k-rows cached in smem
constexpr int KT = kD - KS;                       // 120 tail k-rows in registers
constexpr int RECUR_SMEM = (kD * KS + 8 * kD) * 4;   // Ws + 2x rs buffers = 225600 B
constexpr int OUTG_SMEM = 8 * 3900 * 4;
}

typedef unsigned long long ull;

__device__ __forceinline__ void ffma2(ull& d, ull a, ull b, ull c) {
    asm("fma.rn.f32x2 %0, %1, %2, %3;" : "=l"(d) : "l"(a), "l"(b), "l"(c));
}
__device__ __forceinline__ float pairsum(ull v) {
    float lo = __uint_as_float((unsigned)(v & 0xffffffffu));
    float hi = __uint_as_float((unsigned)(v >> 32));
    return lo + hi;
}
__device__ __forceinline__ ull packf2(float lo, float hi) {
    ull r; asm("mov.b64 %0, {%1, %2};" : "=l"(r) : "f"(lo), "f"(hi)); return r;
}
__device__ __forceinline__ uint32_t f2tf32(float x) {
    uint32_t u; asm("cvt.rna.tf32.f32 %0, %1;" : "=r"(u) : "f"(x)); return u;
}
__device__ __forceinline__ void mma_tf32(float c[4], const uint32_t a[4], const uint32_t b[2]) {
    asm("mma.sync.aligned.m16n8k8.row.col.f32.tf32.tf32.f32 "
        "{%0,%1,%2,%3},{%4,%5,%6,%7},{%8,%9},{%0,%1,%2,%3};"
        : "+f"(c[0]), "+f"(c[1]), "+f"(c[2]), "+f"(c[3])
        : "r"(a[0]), "r"(a[1]), "r"(a[2]), "r"(a[3]), "r"(b[0]), "r"(b[1]));
}

__device__ float g_U[(size_t)kL * kB * kD];  // [t][b][j]
__device__ float g_A[kDin * kD];             // in_W @ Wh0
__device__ float g_c0[kD];                   // in_b @ Wh0 + lb0
__device__ float g_WrT[kD * kD];             // Wr0^T: [j][k]
__device__ float g_x0[kB * kD];
__device__ float g_skip[kB * kDin];
__device__ float g_cpre[kB * kDin];

__global__ void prep_kernel(const float* __restrict__ in_W, const float* __restrict__ in_b,
                            const float* __restrict__ Wh, const float* __restrict__ Wr,
                            const float* __restrict__ lb) {
    int idx = blockIdx.x * blockDim.x + threadIdx.x;
    if (idx < kDin * kD) {
        int d = idx / kD, j = idx % kD;
        const float* iw = in_W + (size_t)d * kD;
        float s = 0.f;
        for (int k = 0; k < kD; k++) s += iw[k] * Wh[k * kD + j];
        g_A[idx] = s;
    } else if (idx < kDin * kD + kD * kD) {
        int t = idx - kDin * kD;
        int j = t / kD, k = t % kD;
        g_WrT[t] = Wr[k * kD + j];
    } else if (idx < kDin * kD + kD * kD + kD) {
        int j = idx - kDin * kD - kD * kD;
        float s = lb[j];
        for (int k = 0; k < kD; k++) s += in_b[k] * Wh[k * kD + j];
        g_c0[j] = s;
    }
}

// ---------------------------------------------------------------------------
// U = WE @ g_A + g_c0 via tf32 mma.sync m16n8k8.
// CTA: BM=128, BN=64, BK=32; 8 warps as 4m x 2n; warp tile 32x32 = 2x4 mma.
// Fragment-major smem: scatter at fill so fragment reads are contiguous
// LDS.128 (A) / LDS.64 (B). Out row permuted: rin=b*256+l -> orow=l*512+b.
// ---------------------------------------------------------------------------
__global__ __launch_bounds__(256) void gemm_u_kernel(const float* __restrict__ we) {
    __shared__ uint32_t Af[4][8][128];  // [k8][m16-tile][lane*4+frag]
    __shared__ uint32_t Bf[4][8][64];   // [k8][n8-tile][lane*2+frag]
    int tid = threadIdx.x, wid = tid >> 5, lane = tid & 31;
    int row0 = blockIdx.y * 128, col0 = blockIdx.x * 64;
    int wm = wid >> 1, wn = wid & 1;

    float c[2][4][4];
#pragma unroll
    for (int mt = 0; mt < 2; mt++)
#pragma unroll
        for (int nt = 0; nt < 4; nt++)
#pragma unroll
            for (int f = 0; f < 4; f++) c[mt][nt][f] = 0.f;

    for (int k0 = 0; k0 < kDin; k0 += 32) {
        __syncthreads();
        // A fill: 128m x 32k, 4 float4 per thread (coalesced along k)
#pragma unroll
        for (int i = 0; i < 4; i++) {
            int fid = tid + i * 256;          // 0..1023
            int m = fid >> 3, kq = (fid & 7) * 4;
            float4 v = *(const float4*)&we[(size_t)(row0 + m) * kDin + k0 + kq];
            float vv[4] = {v.x, v.y, v.z, v.w};
#pragma unroll
            for (int j = 0; j < 4; j++) {
                int k = kq + j;
                int k8 = k >> 3, cc = k & 7;
                int r = m & 15, mt = m >> 4;
                int ln = (r & 7) * 4 + (cc & 3);
                int f = ((cc >> 2) << 1) + (r >> 3);
                Af[k8][mt][ln * 4 + f] = f2tf32(vv[j]);
            }
        }
        // B fill: 32k x 64n, 2 float4 per thread (coalesced along n), col guard
#pragma unroll
        for (int i = 0; i < 2; i++) {
            int fid = tid + i * 256;          // 0..511
            int k = fid >> 4, nq = (fid & 15) * 4;
            int col = col0 + nq;
            float4 v = make_float4(0.f, 0.f, 0.f, 0.f);
            if (col + 3 < kD) v = *(const float4*)&g_A[(size_t)(k0 + k) * kD + col];
            else {
                if (col     < kD) v.x = g_A[(k0 + k) * kD + col];
                if (col + 1 < kD) v.y = g_A[(k0 + k) * kD + col + 1];
                if (col + 2 < kD) v.z = g_A[(k0 + k) * kD + col + 2];
            }
            float vv[4] = {v.x, v.y, v.z, v.w};
#pragma unroll
            for (int j = 0; j < 4; j++) {
                int n = nq + j;               // local col 0..63
                int k8 = k >> 3;
                int ln = (n & 7) * 4 + (k & 3);
                int f = (k >> 2) & 1;
                Bf[k8][n >> 3][ln * 2 + f] = f2tf32(vv[j]);
            }
        }
        __syncthreads();
#pragma unroll
        for (int k8 = 0; k8 < 4; k8++) {
            uint32_t a[2][4];
#pragma unroll
            for (int mt = 0; mt < 2; mt++)
                *(uint4*)a[mt] = *(const uint4*)&Af[k8][wm * 2 + mt][lane * 4];
            uint32_t b[4][2];
#pragma unroll
            for (int nt = 0; nt < 4; nt++)
                *(uint2*)b[nt] = *(const uint2*)&Bf[k8][wn * 4 + nt][lane * 2];
#pragma unroll
            for (int mt = 0; mt < 2; mt++)
#pragma unroll
                for (int nt = 0; nt < 4; nt++) mma_tf32(c[mt][nt], a[mt], b[nt]);
        }
    }

    // epilogue: c frag (r,cidx): c0:(g, q*2) c1:(g, q*2+1) c2:(g+8,..) c3
    int g = lane >> 2, q = lane & 3;
#pragma unroll
    for (int mt = 0; mt < 2; mt++) {
#pragma unroll
        for (int hh = 0; hh < 2; hh++) {
            int rloc = wm * 32 + mt * 16 + g + hh * 8;
            int rin = row0 + rloc;
            int orow = ((rin & 255) << 9) + (rin >> 8);
            float* op = g_U + (size_t)orow * kD;
#pragma unroll
            for (int nt = 0; nt < 4; nt++) {
                int col = col0 + wn * 32 + nt * 8 + q * 2;
                if (col < kD) {
                    op[col]     = c[mt][nt][hh * 2 + 0] + g_c0[col];
                    op[col + 1] = c[mt][nt][hh * 2 + 1] + g_c0[col + 1];
                }
            }
        }
    }
}

// ---------------------------------------------------------------------------
// Recurrence (unchanged from R9-pass): 128 CTAs x 4 batch rows.
// ---------------------------------------------------------------------------
__global__ __launch_bounds__(320, 1) void recur_kernel(float* __restrict__ mem) {
    extern __shared__ float sm[];
    float* Ws  = sm;                 // [j][KS]
    float* rsA = sm + kD * KS;       // [4][kD]
    float* rsB = rsA + 4 * kD;       // [4][kD]
    int tid = threadIdx.x;
    int b0 = blockIdx.x * 4;

    for (int idx = tid; idx < kD * (KS / 4); idx += blockDim.x) {
        int j = idx / (KS / 4), q = idx % (KS / 4);
        *(float4*)&Ws[j * KS + q * 4] = *(const float4*)&g_WrT[(size_t)j * kD + q * 4];
    }
    for (int idx = tid; idx < 4 * kD; idx += blockDim.x) { rsA[idx] = 0.f; rsB[idx] = 0.f; }

    const int j = tid;
    const bool act = (j < kD);

    ulonglong2 wr[KT / 4];
    if (act) {
#pragma unroll
        for (int i = 0; i < KT / 4; i++)
            wr[i] = *(const ulonglong2*)&g_WrT[(size_t)j * kD + KS + 4 * i];
    }
    __syncthreads();

    float* m0 = mem + (size_t)b0 * kMemRow;
    const float inv13 = 1.f / 13.f;
    float* ra = rsA;
    float* rb = rsB;

    for (int t = 0; t < kL; t++) {
        int ptr = t % 13;
        if (act) {
            const float* up = g_U + ((size_t)t * kB + b0) * kD + j;
            float u0 = up[0], u1 = up[kD], u2 = up[2 * kD], u3 = up[3 * kD];
            float* ms = m0 + ptr * 2400 + j;
            float o0 = ms[0], o1 = ms[kMemRow], o2 = ms[2 * kMemRow], o3 = ms[3 * kMemRow];

            ull a0x = 0, a0y = 0, a1x = 0, a1y = 0, a2x = 0, a2y = 0, a3x = 0, a3y = 0;
            const ulonglong2* wp  = (const ulonglong2*)(Ws + j * KS);
            const ulonglong2* r0p = (const ulonglong2*)(ra);
            const ulonglong2* r1p = (const ulonglong2*)(ra + kD);
            const ulonglong2* r2p = (const ulonglong2*)(ra + 2 * kD);
            const ulonglong2* r3p = (const ulonglong2*)(ra + 3 * kD);
#pragma unroll
            for (int q = 0; q < KS / 4; q++) {
                ulonglong2 w = wp[q];
                ulonglong2 q0 = r0p[q], q1 = r1p[q], q2 = r2p[q], q3 = r3p[q];
                ffma2(a0x, q0.x, w.x, a0x); ffma2(a0y, q0.y, w.y, a0y);
                ffma2(a1x, q1.x, w.x, a1x); ffma2(a1y, q1.y, w.y, a1y);
                ffma2(a2x, q2.x, w.x, a2x); ffma2(a2y, q2.y, w.y, a2y);
                ffma2(a3x, q3.x, w.x, a3x); ffma2(a3y, q3.y, w.y, a3y);
            }
#pragma unroll
            for (int q = 0; q < KT / 4; q++) {
                ulonglong2 w = wr[q];
                ulonglong2 q0 = r0p[KS / 4 + q], q1 = r1p[KS / 4 + q];
                ulonglong2 q2 = r2p[KS / 4 + q], q3 = r3p[KS / 4 + q];
                ffma2(a0x, q0.x, w.x, a0x); ffma2(a0y, q0.y, w.y, a0y);
                ffma2(a1x, q1.x, w.x, a1x); ffma2(a1y, q1.y, w.y, a1y);
                ffma2(a2x, q2.x, w.x, a2x); ffma2(a2y, q2.y, w.y, a2y);
                ffma2(a3x, q3.x, w.x, a3x); ffma2(a3y, q3.y, w.y, a3y);
            }
            float h0 = tanhf(u0 + (pairsum(a0x) + pairsum(a0y)) * inv13);
            float h1 = tanhf(u1 + (pairsum(a1x) + pairsum(a1y)) * inv13);
            float h2 = tanhf(u2 + (pairsum(a2x) + pairsum(a2y)) * inv13);
            float h3 = tanhf(u3 + (pairsum(a3x) + pairsum(a3y)) * inv13);
            ms[0]           = h0;
            ms[kMemRow]     = h1;
            ms[2 * kMemRow] = h2;
            ms[3 * kMemRow] = h3;
            rb[j]          = ra[j]          + (h0 - o0);
            rb[kD + j]     = ra[kD + j]     + (h1 - o1);
            rb[2 * kD + j] = ra[2 * kD + j] + (h2 - o2);
            rb[3 * kD + j] = ra[3 * kD + j] + (h3 - o3);
        }
        __syncthreads();
        float* tmp = ra; ra = rb; rb = tmp;
    }
}

__global__ void x0_kernel(const float* __restrict__ we, const float* __restrict__ in_W,
                          const float* __restrict__ in_b) {
    int idx = blockIdx.x * blockDim.x + threadIdx.x;
    if (idx >= kB * kD) return;
    int b = idx / kD, j = idx % kD;
    const float* wr = we + (size_t)b * kL * kDin;
    float s = in_b[j];
    for (int d = 0; d < kDin; d++) s += wr[d] * in_W[d * kD + j];
    g_x0[idx] = s;
}

__global__ void skip_kernel(const float* __restrict__ skip_W, const float* __restrict__ skip_b) {
    int idx = blockIdx.x * blockDim.x + threadIdx.x;
    if (idx >= kB * kDin) return;
    int b = idx / kDin, i = idx % kDin;
    const float* x = g_x0 + (size_t)b * kD;
    float s = skip_b[i];
    for (int jj = 0; jj < kD; jj++) s += x[jj] * skip_W[jj * kDin + i];
    g_skip[idx] = s;
}

__global__ void outgemm_kernel(const float* __restrict__ mem, const float* __restrict__ outW) {
    extern __shared__ float X[];  // [8][3900]
    int b0 = blockIdx.x * 8, tid = threadIdx.x;
    for (int idx = tid; idx < 8 * 3900; idx += 384) {
        int r = idx / 3900, k = idx % 3900;
        int s = k / 300, d = k % 300;
        X[idx] = mem[(size_t)(b0 + r) * kMemRow + s * 2400 + d];
    }
    __syncthreads();
    int i = tid;
    ull accx[8], accy[8];
#pragma unroll
    for (int r = 0; r < 8; r++) { accx[r] = 0ull; accy[r] = 0ull; }
    for (int s = 0; s < 13; s++) {
        const float* wb = outW + (size_t)s * 2400 * kDin + i;
        const float* Xs = X + s * 300;
        for (int d4 = 0; d4 < 75; d4++) {
            float w0 = wb[(size_t)(d4 * 4 + 0) * kDin];
            float w1 = wb[(size_t)(d4 * 4 + 1) * kDin];
            float w2 = wb[(size_t)(d4 * 4 + 2) * kDin];
            float w3 = wb[(size_t)(d4 * 4 + 3) * kDin];
            ull w01 = packf2(w0, w1), w23 = packf2(w2, w3);
#pragma unroll
            for (int r = 0; r < 8; r++) {
                ulonglong2 x = *(const ulonglong2*)&Xs[r * 3900 + d4 * 4];
                ffma2(accx[r], x.x, w01, accx[r]);
                ffma2(accy[r], x.y, w23, accy[r]);
            }
        }
    }
#pragma unroll
    for (int r = 0; r < 8; r++)
        g_cpre[(size_t)(b0 + r) * kDin + i] = pairsum(accx[r]) + pairsum(accy[r]);
}

__global__ void final_kernel(const float* __restrict__ out_b,
                             const float* __restrict__ ln_g, const float* __restrict__ ln_b,
                             const float* __restrict__ W1, const float* __restrict__ b1,
                             const float* __restrict__ W2, const float* __restrict__ b2,
                             float* __restrict__ out) {
    __shared__ float cv[kDin];
    __shared__ float red[16];
    __shared__ float hid[64];
    int b = blockIdx.x, tid = threadIdx.x;
    int lane = tid & 31, wid = tid >> 5;

    float v = g_cpre[(size_t)b * kDin + tid] + out_b[tid] + g_skip[(size_t)b * kDin + tid];

    float s = v;
#pragma unroll
    for (int o = 16; o > 0; o >>= 1) s += __shfl_xor_sync(0xffffffffu, s, o);
    if (lane == 0) red[wid] = s;
    __syncthreads();
    if (tid == 0) {
        float t = 0.f;
        for (int w = 0; w < 12; w++) t += red[w];
        red[12] = t / kDin;
    }
    __syncthreads();
    float mu = red[12];
    float dv = v - mu;
    float s2 = dv * dv;
#pragma unroll
    for (int o = 16; o > 0; o >>= 1) s2 += __shfl_xor_sync(0xffffffffu, s2, o);
    if (lane == 0) red[wid] = s2;
    __syncthreads();
    if (tid == 0) {
        float t = 0.f;
        for (int w = 0; w < 12; w++) t += red[w];
        red[13] = rsqrtf(t / kDin + 1e-5f);
    }
    __syncthreads();
    float c = dv * red[13] * ln_g[tid] + ln_b[tid];
    out[(size_t)b * kDin + tid] = c;
    cv[tid] = c;
    __syncthreads();

    if (tid < 64) {
        float a = b1[tid];
        for (int d = 0; d < kDin; d++) a += cv[d] * W1[(size_t)d * 64 + tid];
        hid[tid] = fmaxf(a, 0.f) * W2[tid];
    }
    __syncthreads();
    if (tid == 0) {
        float lg = b2[0];
        for (int h = 0; h < 64; h++) lg += hid[h];
        out[kLogitOff + b] = lg;
    }
}

extern "C" void kernel_launch(void* const* d_in, const int* in_sizes, int n_in,
                              void* d_out, int out_size) {
    const float* we     = (const float*)d_in[0];
    const float* in_W   = (const float*)d_in[1];
    const float* in_b   = (const float*)d_in[2];
    const float* Wh     = (const float*)d_in[3];
    const float* Wr     = (const float*)d_in[4];
    const float* lb     = (const float*)d_in[5];
    const float* skip_W = (const float*)d_in[6];
    const float* skip_b = (const float*)d_in[7];
    const float* out_W  = (const float*)d_in[8];
    const float* out_b  = (const float*)d_in[9];
    const float* ln_g   = (const float*)d_in[10];
    const float* ln_b   = (const float*)d_in[11];
    const float* sh_W1  = (const float*)d_in[12];
    const float* sh_b1  = (const float*)d_in[13];
    const float* sh_W2  = (const float*)d_in[14];
    const float* sh_b2  = (const float*)d_in[15];
    float* out = (float*)d_out;

    cudaFuncSetAttribute(recur_kernel, cudaFuncAttributeMaxDynamicSharedMemorySize, RECUR_SMEM);
    cudaFuncSetAttribute(outgemm_kernel, cudaFuncAttributeMaxDynamicSharedMemorySize, OUTG_SMEM);

    cudaMemsetAsync(out + kMemOff, 0, (size_t)kB * kMemRow * sizeof(float));       // item 1

    {
        int total = kDin * kD + kD * kD + kD;
        prep_kernel<<<(total + 255) / 256, 256>>>(in_W, in_b, Wh, Wr, lb);          // item 2
    }
    x0_kernel<<<(kB * kD + 255) / 256, 256>>>(we, in_W, in_b);                      // item 3
    skip_kernel<<<(kB * kDin + 255) / 256, 256>>>(skip_W, skip_b);                  // item 4
    {
        dim3 grid(5, (kB * kL) / 128);  // 5 n-blocks x 1024 m-blocks
        gemm_u_kernel<<<grid, 256>>>(we);                                           // item 5 (ncu slot)
    }
    recur_kernel<<<kB / 4, 320, RECUR_SMEM>>>(out + kMemOff);

    outgemm_kernel<<<kB / 8, 384, OUTG_SMEM>>>(out + kMemOff, out_W);

    final_kernel<<<kB, kDin>>>(out_b, ln_g, ln_b, sh_W1, sh_b1, sh_W2, sh_b2, out);
}